// round 3
// baseline (speedup 1.0000x reference)
#include <cuda_runtime.h>

// IDWT1D Haar inverse reduced to a streaming elementwise map (R0 analysis):
//   out[2k]   = a_k*lo1 + d_k*hi1
//   out[2k+1] = a_k*lo0 + d_k*hi0
// with (a_k,d_k) at input linear offset 2k. Identical in/out addressing ->
// pure float4 stream, zero reuse, HBM-bound.
// R3: 8x float4 per thread (longer read burst / write burst per warp pass to
// cut HBM read<->write bus turnaround), in-place compute to cap registers,
// streaming cache hints retained.

__global__ void __launch_bounds__(256)
idwt_haar_kernel(const float4* __restrict__ in, float4* __restrict__ out,
                 const float* __restrict__ lo, const float* __restrict__ hi,
                 long long n4)
{
    const float lo0 = __ldg(lo + 0);
    const float lo1 = __ldg(lo + 1);
    const float hi0 = __ldg(hi + 0);
    const float hi1 = __ldg(hi + 1);

    const int T = 256;
    long long base = (long long)blockIdx.x * (8 * T) + threadIdx.x;

    if (base + 7LL * T < n4) {
        float4 v[8];
        // Front-batched loads: 8 outstanding LDG.128 per thread.
        #pragma unroll
        for (int k = 0; k < 8; k++)
            v[k] = __ldcs(in + base + (long long)k * T);

        // Compute in place (keeps live registers = 32 value regs).
        #pragma unroll
        for (int k = 0; k < 8; k++) {
            float ax = v[k].x, dx = v[k].y, az = v[k].z, dz = v[k].w;
            v[k].x = ax * lo1 + dx * hi1;
            v[k].y = ax * lo0 + dx * hi0;
            v[k].z = az * lo1 + dz * hi1;
            v[k].w = az * lo0 + dz * hi0;
        }

        // Back-batched stores: long pure-write burst.
        #pragma unroll
        for (int k = 0; k < 8; k++)
            __stcs(out + base + (long long)k * T, v[k]);
    } else {
        // Tail (not taken for bench shape: n4 = 2^24 divisible by 2048).
        #pragma unroll
        for (int k = 0; k < 8; k++) {
            long long i = base + (long long)k * T;
            if (i < n4) {
                float4 v = __ldcs(in + i);
                float4 r;
                r.x = v.x * lo1 + v.y * hi1;  r.y = v.x * lo0 + v.y * hi0;
                r.z = v.z * lo1 + v.w * hi1;  r.w = v.z * lo0 + v.w * hi0;
                __stcs(out + i, r);
            }
        }
    }
}

extern "C" void kernel_launch(void* const* d_in, const int* in_sizes, int n_in,
                              void* d_out, int out_size)
{
    const float* x  = (const float*)d_in[0];
    const float* lo = (const float*)d_in[1];
    const float* hi = (const float*)d_in[2];
    float* out = (float*)d_out;

    long long n_floats = (long long)in_sizes[0];
    long long n4 = n_floats / 4;

    const int threads = 256;
    const long long per_block = 8LL * threads;   // 8 float4 per thread
    int blocks = (int)((n4 + per_block - 1) / per_block);

    idwt_haar_kernel<<<blocks, threads>>>((const float4*)x, (float4*)out,
                                          lo, hi, n4);
}

// round 4
// speedup vs baseline: 1.0055x; 1.0055x over previous
#include <cuda_runtime.h>

// IDWT1D Haar inverse, algebraically reduced (R0 analysis) to a streaming
// elementwise map at identical linear offsets:
//   out[2k]   = a_k*lo1 + d_k*hi1
//   out[2k+1] = a_k*lo0 + d_k*hi0
// with (a_k, d_k) packed at input offset 2k. Pure float4 stream, zero reuse.
//
// FINAL: MLP=4 float4/thread + streaming hints. Measured 74.9us kernel =
// 6.8 TB/s L2-side traffic, at the B300 full-chip LTS cap (~6300 B/cyc,
// path-independent). MLP=2 (75.4us) and MLP=8 (75.7us) both measured worse;
// traffic is irreducible, so this is the roofline.

__global__ void __launch_bounds__(256)
idwt_haar_kernel(const float4* __restrict__ in, float4* __restrict__ out,
                 const float* __restrict__ lo, const float* __restrict__ hi,
                 long long n4)
{
    const float lo0 = __ldg(lo + 0);
    const float lo1 = __ldg(lo + 1);
    const float hi0 = __ldg(hi + 0);
    const float hi1 = __ldg(hi + 1);

    const int T = 256;
    long long base = (long long)blockIdx.x * (4 * T) + threadIdx.x;

    if (base + 3LL * T < n4) {
        // Front-batched loads (MLP=4), compute, back-batched stores.
        float4 v0 = __ldcs(in + base);
        float4 v1 = __ldcs(in + base + T);
        float4 v2 = __ldcs(in + base + 2 * T);
        float4 v3 = __ldcs(in + base + 3 * T);

        float4 r0, r1, r2, r3;
        r0.x = v0.x * lo1 + v0.y * hi1;  r0.y = v0.x * lo0 + v0.y * hi0;
        r0.z = v0.z * lo1 + v0.w * hi1;  r0.w = v0.z * lo0 + v0.w * hi0;

        r1.x = v1.x * lo1 + v1.y * hi1;  r1.y = v1.x * lo0 + v1.y * hi0;
        r1.z = v1.z * lo1 + v1.w * hi1;  r1.w = v1.z * lo0 + v1.w * hi0;

        r2.x = v2.x * lo1 + v2.y * hi1;  r2.y = v2.x * lo0 + v2.y * hi0;
        r2.z = v2.z * lo1 + v2.w * hi1;  r2.w = v2.z * lo0 + v2.w * hi0;

        r3.x = v3.x * lo1 + v3.y * hi1;  r3.y = v3.x * lo0 + v3.y * hi0;
        r3.z = v3.z * lo1 + v3.w * hi1;  r3.w = v3.z * lo0 + v3.w * hi0;

        __stcs(out + base,         r0);
        __stcs(out + base + T,     r1);
        __stcs(out + base + 2 * T, r2);
        __stcs(out + base + 3 * T, r3);
    } else {
        // Tail (not taken for bench shape: n4 = 2^24, divisible by 1024).
        #pragma unroll
        for (int k = 0; k < 4; k++) {
            long long i = base + (long long)k * T;
            if (i < n4) {
                float4 v = __ldcs(in + i);
                float4 r;
                r.x = v.x * lo1 + v.y * hi1;  r.y = v.x * lo0 + v.y * hi0;
                r.z = v.z * lo1 + v.w * hi1;  r.w = v.z * lo0 + v.w * hi0;
                __stcs(out + i, r);
            }
        }
    }
}

extern "C" void kernel_launch(void* const* d_in, const int* in_sizes, int n_in,
                              void* d_out, int out_size)
{
    const float* x  = (const float*)d_in[0];
    const float* lo = (const float*)d_in[1];
    const float* hi = (const float*)d_in[2];
    float* out = (float*)d_out;

    long long n_floats = (long long)in_sizes[0];
    long long n4 = n_floats / 4;

    const int threads = 256;
    const long long per_block = 4LL * threads;   // 4 float4 per thread
    int blocks = (int)((n4 + per_block - 1) / per_block);

    idwt_haar_kernel<<<blocks, threads>>>((const float4*)x, (float4*)out,
                                          lo, hi, n4);
}